// round 1
// baseline (speedup 1.0000x reference)
#include <cuda_runtime.h>
#include <cuda_bf16.h>

// SSIM loss, fused single-pass tiled kernel.
// pred, target: (16,3,512,512) f32.  Output: scalar f32 = 1 - mean(ssim_map).
// Gaussian 11x11, sigma=1.5, separable. Zero padding (matches lax.conv pad=5).

#define IMG_H 512
#define IMG_W 512
#define NCHAN 48            // 16 * 3
#define TILE 32
#define HALO 5
#define IN_T (TILE + 2*HALO)   // 42
#define SP_STRIDE 43           // 42 + 1 pad (conflict-free)
#define SH_STRIDE 33           // 32 + 1 pad (conflict-free)
#define NBLOCKS (16*16*48)     // 12288
#define NPIX (16.0*3.0*512.0*512.0)

// 1D gaussian, sigma=1.5, normalized (precomputed, symmetric)
__constant__ float W11[11] = {
    0.00102838f, 0.00759876f, 0.03600077f, 0.10936068f, 0.21300557f,
    0.26601170f,
    0.21300557f, 0.10936068f, 0.03600077f, 0.00759876f, 0.00102838f
};

__device__ float g_part[NBLOCKS];

__global__ __launch_bounds__(256)
void ssim_tile_kernel(const float* __restrict__ pred,
                      const float* __restrict__ targ)
{
    __shared__ float sP[IN_T * SP_STRIDE];
    __shared__ float sQ[IN_T * SP_STRIDE];
    __shared__ float sH[5][IN_T * SH_STRIDE];   // horizontal-convolved strips
    __shared__ float warpsum[8];

    const int tid = threadIdx.x;
    const int bx = blockIdx.x, by = blockIdx.y, bz = blockIdx.z;

    const float* __restrict__ p = pred + (size_t)bz * (IMG_H * IMG_W);
    const float* __restrict__ q = targ + (size_t)bz * (IMG_H * IMG_W);

    const int gx0 = bx * TILE - HALO;
    const int gy0 = by * TILE - HALO;

    // ---- load 42x42 halo tiles of pred & target (zero-padded) ----
    for (int i = tid; i < IN_T * IN_T; i += 256) {
        int r = i / IN_T, c = i - r * IN_T;
        int gy = gy0 + r, gx = gx0 + c;
        float pv = 0.f, qv = 0.f;
        if ((unsigned)gy < IMG_H && (unsigned)gx < IMG_W) {
            int o = gy * IMG_W + gx;
            pv = p[o]; qv = q[o];
        }
        sP[r * SP_STRIDE + c] = pv;
        sQ[r * SP_STRIDE + c] = qv;
    }
    __syncthreads();

    // ---- horizontal pass: 42 rows x 8 col-groups of 4 cols, 5 maps ----
    // maps: 0=x, 1=y, 2=x*x, 3=y*y, 4=x*y  (products formed on the fly)
    for (int t = tid; t < IN_T * 8; t += 256) {
        int r  = t >> 3;
        int cg = (t & 7) << 2;       // output col base: 0,4,...,28

        float pv[14], qv[14];
        #pragma unroll
        for (int j = 0; j < 14; j++) {
            pv[j] = sP[r * SP_STRIDE + cg + j];
            qv[j] = sQ[r * SP_STRIDE + cg + j];
        }

        float ax[4]  = {0,0,0,0}, ay[4]  = {0,0,0,0};
        float axx[4] = {0,0,0,0}, ayy[4] = {0,0,0,0}, axy[4] = {0,0,0,0};
        #pragma unroll
        for (int j = 0; j < 14; j++) {
            float pp = pv[j] * pv[j];
            float qq = qv[j] * qv[j];
            float pq = pv[j] * qv[j];
            #pragma unroll
            for (int k = 0; k < 4; k++) {
                int tap = j - k;
                if (tap >= 0 && tap < 11) {
                    float w = W11[tap];
                    ax[k]  += w * pv[j];
                    ay[k]  += w * qv[j];
                    axx[k] += w * pp;
                    ayy[k] += w * qq;
                    axy[k] += w * pq;
                }
            }
        }
        #pragma unroll
        for (int k = 0; k < 4; k++) {
            sH[0][r * SH_STRIDE + cg + k] = ax[k];
            sH[1][r * SH_STRIDE + cg + k] = ay[k];
            sH[2][r * SH_STRIDE + cg + k] = axx[k];
            sH[3][r * SH_STRIDE + cg + k] = ayy[k];
            sH[4][r * SH_STRIDE + cg + k] = axy[k];
        }
    }
    __syncthreads();

    // ---- vertical pass + SSIM pointwise: each thread -> 4 rows of one col ----
    const int tx = tid & 31;
    const int ty = tid >> 5;          // 0..7
    const int y0 = ty << 2;           // 0,4,...,28

    float res[5][4];
    #pragma unroll
    for (int m = 0; m < 5; m++) {
        float v[14];
        #pragma unroll
        for (int j = 0; j < 14; j++)
            v[j] = sH[m][(y0 + j) * SH_STRIDE + tx];
        #pragma unroll
        for (int k = 0; k < 4; k++) {
            float a = 0.f;
            #pragma unroll
            for (int tap = 0; tap < 11; tap++)
                a += W11[tap] * v[k + tap];
            res[m][k] = a;
        }
    }

    const float C1 = 1e-4f, C2 = 9e-4f;
    float local = 0.f;
    #pragma unroll
    for (int k = 0; k < 4; k++) {
        float mx = res[0][k], my = res[1][k];
        float mxs = mx * mx, mys = my * my, mxy = mx * my;
        float sx  = res[2][k] - mxs;
        float sy  = res[3][k] - mys;
        float sxy = res[4][k] - mxy;
        float num = (2.f * mxy + C1) * (2.f * sxy + C2);
        float den = (mxs + mys + C1) * (sx + sy + C2);
        local += num / den;
    }

    // ---- block reduction ----
    #pragma unroll
    for (int o = 16; o > 0; o >>= 1)
        local += __shfl_down_sync(0xFFFFFFFFu, local, o);
    if ((tid & 31) == 0) warpsum[tid >> 5] = local;
    __syncthreads();
    if (tid == 0) {
        float s = 0.f;
        #pragma unroll
        for (int i = 0; i < 8; i++) s += warpsum[i];
        g_part[(bz * 16 + by) * 16 + bx] = s;
    }
}

__global__ void ssim_finish_kernel(float* __restrict__ out)
{
    __shared__ double sd[256];
    double s = 0.0;
    for (int i = threadIdx.x; i < NBLOCKS; i += 256)
        s += (double)g_part[i];
    sd[threadIdx.x] = s;
    __syncthreads();
    for (int o = 128; o > 0; o >>= 1) {
        if (threadIdx.x < o) sd[threadIdx.x] += sd[threadIdx.x + o];
        __syncthreads();
    }
    if (threadIdx.x == 0)
        out[0] = (float)(1.0 - sd[0] / NPIX);
}

extern "C" void kernel_launch(void* const* d_in, const int* in_sizes, int n_in,
                              void* d_out, int out_size)
{
    const float* pred = (const float*)d_in[0];
    const float* targ = (const float*)d_in[1];
    float* out = (float*)d_out;

    dim3 grid(16, 16, NCHAN);   // 16x16 tiles per 512x512 image, 48 channel-images
    ssim_tile_kernel<<<grid, 256>>>(pred, targ);
    ssim_finish_kernel<<<1, 256>>>(out);
}